// round 1
// baseline (speedup 1.0000x reference)
#include <cuda_runtime.h>
#include <math.h>

// Model dims
#define NB   2
#define NT   2048
#define ND   768
#define NH   12
#define NHS  64
#define NL   6
#define NV   50257
#define NTOK (NB*NT)        // 4096
#define NQKV (3*ND)         // 2304
#define NFF  (4*ND)         // 3072

// ---------------- scratch (static device memory; no allocations) -----------
__device__ float g_x[NTOK*ND];
__device__ float g_h[NTOK*ND];
__device__ float g_qkv[(size_t)NTOK*NQKV];
__device__ float g_o[NTOK*ND];
__device__ float g_mlp[(size_t)NTOK*NFF];
__device__ float g_wqkv[(size_t)NL*ND*NQKV];
__device__ float g_loss;

// ---------------- small utility kernels ------------------------------------
__global__ void reset_loss_kernel() { g_loss = 0.0f; }

__global__ void repack_qkv_kernel(const float* __restrict__ wq,
                                  const float* __restrict__ wk,
                                  const float* __restrict__ wv) {
    int i = blockIdx.x * 256 + threadIdx.x;
    const int total = NL * ND * NQKV;
    if (i >= total) return;
    int c = i % NQKV;
    int d = (i / NQKV) % ND;
    int l = i / (NQKV * ND);
    int sec = c / ND;            // 0=q, 1=k, 2=v
    int c2  = c % ND;
    int h   = c2 / NHS;
    int e   = c2 % NHS;
    const float* w = (sec == 0) ? wq : (sec == 1) ? wk : wv;
    g_wqkv[i] = w[(((size_t)l * NH + h) * ND + d) * NHS + e];
}

__global__ void embed_kernel(const int* __restrict__ idx,
                             const float* __restrict__ tok,
                             const float* __restrict__ pos) {
    int i = blockIdx.x * 256 + threadIdx.x;
    if (i >= NTOK * ND) return;
    int d = i % ND;
    int row = i / ND;         // b*NT + t
    int t = row % NT;
    int tokid = idx[row];
    g_x[i] = tok[(size_t)tokid * ND + d] + pos[t * ND + d];
}

// ---------------- layernorm: one block (256 thr) per row, D=768 ------------
__global__ __launch_bounds__(256)
void ln_kernel(const float* __restrict__ x, const float* __restrict__ s,
               const float* __restrict__ b, float* __restrict__ out) {
    __shared__ float red[256];
    int row = blockIdx.x, tid = threadIdx.x;
    const float* xr = x + (size_t)row * ND;
    float v0 = xr[tid], v1 = xr[tid + 256], v2 = xr[tid + 512];
    red[tid] = v0 + v1 + v2;
    __syncthreads();
    for (int off = 128; off; off >>= 1) {
        if (tid < off) red[tid] += red[tid + off];
        __syncthreads();
    }
    float mean = red[0] * (1.0f / ND);
    __syncthreads();
    float d0 = v0 - mean, d1 = v1 - mean, d2 = v2 - mean;
    red[tid] = d0 * d0 + d1 * d1 + d2 * d2;
    __syncthreads();
    for (int off = 128; off; off >>= 1) {
        if (tid < off) red[tid] += red[tid + off];
        __syncthreads();
    }
    float rstd = rsqrtf(red[0] * (1.0f / ND) + 1e-5f);
    float* orow = out + (size_t)row * ND;
    orow[tid]       = d0 * rstd * s[tid]       + b[tid];
    orow[tid + 256] = d1 * rstd * s[tid + 256] + b[tid + 256];
    orow[tid + 512] = d2 * rstd * s[tid + 512] + b[tid + 512];
}

// ---------------- SGEMM: C[MxN] = A[MxK] @ B[KxN] (+bias,+relu,+resid) ------
// 128x128 tile, BK=8, 256 threads, 8x8 per-thread register tile.
// M is always a multiple of 128; N may be ragged (V=50257); K multiple of 8.
#define BM 128
#define BN 128
#define BKK 8
#define TM 8
#define TN 8

template <int EPI>  // bit0: +bias[n], bit1: relu, bit2: +resid[m,n]
__global__ __launch_bounds__(256)
void sgemm_kernel(const float* __restrict__ A, const float* __restrict__ B,
                  const float* __restrict__ bias, const float* __restrict__ resid,
                  float* __restrict__ C, int M, int N, int K) {
    __shared__ float As[BKK][BM];
    __shared__ float Bs[BKK][BN];
    const int tid = threadIdx.x;
    const int tx = tid & 15, ty = tid >> 4;
    const int row0 = blockIdx.y * BM, col0 = blockIdx.x * BN;
    const int a_r = tid >> 1, a_c = (tid & 1) << 2;
    const int b_r = tid >> 5, b_c = (tid & 31) << 2;

    float acc[TM][TN];
#pragma unroll
    for (int i = 0; i < TM; i++)
#pragma unroll
        for (int j = 0; j < TN; j++) acc[i][j] = 0.0f;

    const float* Ag = A + (size_t)(row0 + a_r) * K + a_c;

    for (int k0 = 0; k0 < K; k0 += BKK) {
        float4 av = *reinterpret_cast<const float4*>(Ag + k0);
        As[a_c + 0][a_r] = av.x;
        As[a_c + 1][a_r] = av.y;
        As[a_c + 2][a_r] = av.z;
        As[a_c + 3][a_r] = av.w;
        const float* Bg = B + (size_t)(k0 + b_r) * N + col0 + b_c;
#pragma unroll
        for (int j = 0; j < 4; j++) {
            int n = col0 + b_c + j;
            Bs[b_r][b_c + j] = (n < N) ? Bg[j] : 0.0f;
        }
        __syncthreads();
#pragma unroll
        for (int kk = 0; kk < BKK; kk++) {
            float4 a0 = *reinterpret_cast<const float4*>(&As[kk][ty * TM]);
            float4 a1 = *reinterpret_cast<const float4*>(&As[kk][ty * TM + 4]);
            float4 b0 = *reinterpret_cast<const float4*>(&Bs[kk][tx * TN]);
            float4 b1 = *reinterpret_cast<const float4*>(&Bs[kk][tx * TN + 4]);
            float ar[8] = {a0.x, a0.y, a0.z, a0.w, a1.x, a1.y, a1.z, a1.w};
            float br[8] = {b0.x, b0.y, b0.z, b0.w, b1.x, b1.y, b1.z, b1.w};
#pragma unroll
            for (int i = 0; i < TM; i++)
#pragma unroll
                for (int j = 0; j < TN; j++)
                    acc[i][j] = fmaf(ar[i], br[j], acc[i][j]);
        }
        __syncthreads();
    }

#pragma unroll
    for (int i = 0; i < TM; i++) {
        int m = row0 + ty * TM + i;
#pragma unroll
        for (int j = 0; j < TN; j++) {
            int n = col0 + tx * TN + j;
            if (n < N) {
                float v = acc[i][j];
                if (EPI & 1) v += bias[n];
                if (EPI & 2) v = fmaxf(v, 0.0f);
                if (EPI & 4) v += resid[(size_t)m * N + n];
                C[(size_t)m * N + n] = v;
            }
        }
    }
}

// ---------------- streaming causal attention (warp = 4 queries) ------------
__global__ __launch_bounds__(256)
void attn_kernel(const float* __restrict__ qkv, float* __restrict__ o) {
    int wid = blockIdx.x * 8 + (threadIdx.x >> 5);
    int lane = threadIdx.x & 31;
    const int warps_per_head = NT / 4;  // 512
    int bh = wid / warps_per_head;
    int t0 = (wid % warps_per_head) * 4;
    int b = bh / NH, h = bh % NH;

    const float* base = qkv + (size_t)b * NT * NQKV;
    const float* qb = base + h * NHS;
    const float* kb = base + ND + h * NHS;
    const float* vb = base + 2 * ND + h * NHS;

    float q0[4], q1[4];
#pragma unroll
    for (int i = 0; i < 4; i++) {
        q0[i] = qb[(size_t)(t0 + i) * NQKV + lane];
        q1[i] = qb[(size_t)(t0 + i) * NQKV + 32 + lane];
    }
    float m[4], l[4], a0[4], a1[4];
#pragma unroll
    for (int i = 0; i < 4; i++) { m[i] = -1e30f; l[i] = 0.f; a0[i] = 0.f; a1[i] = 0.f; }

    const float scale = 0.125f;  // HS^-0.5
    int send = t0 + 3;
    for (int s = 0; s <= send; s++) {
        size_t off = (size_t)s * NQKV + lane;
        float k0v = kb[off], k1v = kb[off + 32];
        float v0v = vb[off], v1v = vb[off + 32];
#pragma unroll
        for (int i = 0; i < 4; i++) {
            float p = q0[i] * k0v + q1[i] * k1v;
            p += __shfl_xor_sync(0xffffffffu, p, 16);
            p += __shfl_xor_sync(0xffffffffu, p, 8);
            p += __shfl_xor_sync(0xffffffffu, p, 4);
            p += __shfl_xor_sync(0xffffffffu, p, 2);
            p += __shfl_xor_sync(0xffffffffu, p, 1);
            if (s <= t0 + i) {
                float sc = p * scale;
                float mn = fmaxf(m[i], sc);
                float corr = __expf(m[i] - mn);
                float e = __expf(sc - mn);
                l[i]  = l[i]  * corr + e;
                a0[i] = a0[i] * corr + e * v0v;
                a1[i] = a1[i] * corr + e * v1v;
                m[i] = mn;
            }
        }
    }
#pragma unroll
    for (int i = 0; i < 4; i++) {
        size_t oo = (size_t)(b * NT + t0 + i) * ND + h * NHS + lane;
        o[oo]      = a0[i] / l[i];
        o[oo + 32] = a1[i] / l[i];
    }
}

// ---------------- loss: one block per row over V=50257 ---------------------
__global__ __launch_bounds__(256)
void loss_kernel(const float* __restrict__ logits, const int* __restrict__ targets) {
    __shared__ float sm_[256], sl_[256];
    int row = blockIdx.x, tid = threadIdx.x;
    const float* lr = logits + (size_t)row * NV;
    float m = -1e30f, l = 0.0f;
    for (int j = tid; j < NV; j += 256) {
        float v = lr[j];
        float mn = fmaxf(m, v);
        l = l * __expf(m - mn) + __expf(v - mn);
        m = mn;
    }
    sm_[tid] = m; sl_[tid] = l;
    __syncthreads();
    for (int off = 128; off; off >>= 1) {
        if (tid < off) {
            float m2 = sm_[tid + off], l2 = sl_[tid + off];
            float mn = fmaxf(sm_[tid], m2);
            sl_[tid] = sl_[tid] * __expf(sm_[tid] - mn) + l2 * __expf(m2 - mn);
            sm_[tid] = mn;
        }
        __syncthreads();
    }
    if (tid == 0) {
        float lp = lr[targets[row]] - sm_[0] - logf(sl_[0]);
        atomicAdd(&g_loss, -lp * (1.0f / NTOK));
    }
}

__global__ void finalize_loss_kernel(float* out, int out_size) {
    long long pos = (long long)NTOK * NV;
    if ((long long)out_size > pos) out[pos] = g_loss;
}

// ---------------- host orchestration ----------------------------------------
extern "C" void kernel_launch(void* const* d_in, const int* in_sizes, int n_in,
                              void* d_out, int out_size) {
    const int*   idx     = (const int*)d_in[0];
    const int*   targets = (const int*)d_in[1];
    const float* tok_emb = (const float*)d_in[2];
    const float* pos_emb = (const float*)d_in[3];
    const float* wq      = (const float*)d_in[4];
    const float* wk      = (const float*)d_in[5];
    const float* wv      = (const float*)d_in[6];
    const float* wo      = (const float*)d_in[7];
    const float* bo      = (const float*)d_in[8];
    const float* ln1_s   = (const float*)d_in[9];
    const float* ln1_b   = (const float*)d_in[10];
    const float* ln2_s   = (const float*)d_in[11];
    const float* ln2_b   = (const float*)d_in[12];
    const float* w1      = (const float*)d_in[13];
    const float* b1      = (const float*)d_in[14];
    const float* w2      = (const float*)d_in[15];
    const float* b2      = (const float*)d_in[16];
    const float* lnf_s   = (const float*)d_in[17];
    const float* lnf_b   = (const float*)d_in[18];
    const float* head_w  = (const float*)d_in[19];
    const float* head_b  = (const float*)d_in[20];
    float* out = (float*)d_out;
    (void)in_sizes; (void)n_in;

    float *px, *ph, *pqkv, *po, *pmlp, *pw;
    cudaGetSymbolAddress((void**)&px,   g_x);
    cudaGetSymbolAddress((void**)&ph,   g_h);
    cudaGetSymbolAddress((void**)&pqkv, g_qkv);
    cudaGetSymbolAddress((void**)&po,   g_o);
    cudaGetSymbolAddress((void**)&pmlp, g_mlp);
    cudaGetSymbolAddress((void**)&pw,   g_wqkv);

    reset_loss_kernel<<<1, 1>>>();
    {
        int total = NL * ND * NQKV;
        repack_qkv_kernel<<<(total + 255) / 256, 256>>>(wq, wk, wv);
    }
    {
        int total = NTOK * ND;
        embed_kernel<<<(total + 255) / 256, 256>>>(idx, tok_emb, pos_emb);
    }

    dim3 gQKV((NQKV + BN - 1) / BN, NTOK / BM);
    dim3 gD((ND + BN - 1) / BN, NTOK / BM);
    dim3 gFF((NFF + BN - 1) / BN, NTOK / BM);
    dim3 gV((NV + BN - 1) / BN, NTOK / BM);

    for (int l = 0; l < NL; l++) {
        ln_kernel<<<NTOK, 256>>>(px, ln1_s + l * ND, ln1_b + l * ND, ph);
        sgemm_kernel<0><<<gQKV, 256>>>(ph, pw + (size_t)l * ND * NQKV,
                                       nullptr, nullptr, pqkv, NTOK, NQKV, ND);
        attn_kernel<<<NB * NH * NT / 4 / 8, 256>>>(pqkv, po);
        sgemm_kernel<5><<<gD, 256>>>(po, wo + (size_t)l * ND * ND,
                                     bo + l * ND, px, px, NTOK, ND, ND);
        ln_kernel<<<NTOK, 256>>>(px, ln2_s + l * ND, ln2_b + l * ND, ph);
        sgemm_kernel<3><<<gFF, 256>>>(ph, w1 + (size_t)l * ND * NFF,
                                      b1 + l * NFF, nullptr, pmlp, NTOK, NFF, ND);
        sgemm_kernel<5><<<gD, 256>>>(pmlp, w2 + (size_t)l * NFF * ND,
                                     b2 + l * ND, px, px, NTOK, ND, NFF);
    }

    ln_kernel<<<NTOK, 256>>>(px, lnf_s, lnf_b, ph);
    sgemm_kernel<1><<<gV, 256>>>(ph, head_w, head_b, nullptr, out, NTOK, NV, ND);
    loss_kernel<<<NTOK, 256>>>(out, targets);
    finalize_loss_kernel<<<1, 1>>>(out, out_size);
}

// round 3
// speedup vs baseline: 1.4712x; 1.4712x over previous
#include <cuda_runtime.h>
#include <math.h>

// Model dims
#define NB   2
#define NT   2048
#define ND   768
#define NH   12
#define NHS  64
#define NL   6
#define NV   50257
#define NTOK (NB*NT)        // 4096
#define NQKV (3*ND)         // 2304
#define NFF  (4*ND)         // 3072

// ---------------- scratch (static device memory; no allocations) -----------
__device__ float g_x[NTOK*ND];
__device__ float g_h[NTOK*ND];
__device__ float g_qkv[(size_t)NTOK*NQKV];
__device__ float g_o[NTOK*ND];
__device__ float g_mlp[(size_t)NTOK*NFF];
__device__ float g_wqkv[(size_t)NL*ND*NQKV];
__device__ float g_loss;

// ---------------- small utility kernels ------------------------------------
__global__ void reset_loss_kernel() { g_loss = 0.0f; }

__global__ void repack_qkv_kernel(const float* __restrict__ wq,
                                  const float* __restrict__ wk,
                                  const float* __restrict__ wv) {
    int i = blockIdx.x * 256 + threadIdx.x;
    const int total = NL * ND * NQKV;
    if (i >= total) return;
    int c = i % NQKV;
    int d = (i / NQKV) % ND;
    int l = i / (NQKV * ND);
    int sec = c / ND;            // 0=q, 1=k, 2=v
    int c2  = c % ND;
    int h   = c2 / NHS;
    int e   = c2 % NHS;
    const float* w = (sec == 0) ? wq : (sec == 1) ? wk : wv;
    g_wqkv[i] = w[(((size_t)l * NH + h) * ND + d) * NHS + e];
}

__global__ void embed_kernel(const int* __restrict__ idx,
                             const float* __restrict__ tok,
                             const float* __restrict__ pos) {
    int i = blockIdx.x * 256 + threadIdx.x;
    if (i >= NTOK * ND) return;
    int d = i % ND;
    int row = i / ND;         // b*NT + t
    int t = row % NT;
    int tokid = idx[row];
    g_x[i] = tok[(size_t)tokid * ND + d] + pos[t * ND + d];
}

// ---------------- layernorm: one block (256 thr) per row, D=768 ------------
__global__ __launch_bounds__(256)
void ln_kernel(const float* __restrict__ x, const float* __restrict__ s,
               const float* __restrict__ b, float* __restrict__ out) {
    __shared__ float red[256];
    int row = blockIdx.x, tid = threadIdx.x;
    const float* xr = x + (size_t)row * ND;
    float v0 = xr[tid], v1 = xr[tid + 256], v2 = xr[tid + 512];
    red[tid] = v0 + v1 + v2;
    __syncthreads();
    for (int off = 128; off; off >>= 1) {
        if (tid < off) red[tid] += red[tid + off];
        __syncthreads();
    }
    float mean = red[0] * (1.0f / ND);
    __syncthreads();
    float d0 = v0 - mean, d1 = v1 - mean, d2 = v2 - mean;
    red[tid] = d0 * d0 + d1 * d1 + d2 * d2;
    __syncthreads();
    for (int off = 128; off; off >>= 1) {
        if (tid < off) red[tid] += red[tid + off];
        __syncthreads();
    }
    float rstd = rsqrtf(red[0] * (1.0f / ND) + 1e-5f);
    float* orow = out + (size_t)row * ND;
    orow[tid]       = d0 * rstd * s[tid]       + b[tid];
    orow[tid + 256] = d1 * rstd * s[tid + 256] + b[tid + 256];
    orow[tid + 512] = d2 * rstd * s[tid + 512] + b[tid + 512];
}

// ---------------- TF32 tensor-core GEMM ------------------------------------
// C[MxN] = A[MxK] @ B[KxN] (+bias, +relu, +resid)
// Block 128x128, BK=16, 256 threads = 8 warps (2x4), warp tile 64x32.
// mma.sync.aligned.m16n8k8.row.col.f32.tf32.tf32.f32
// M multiple of 128, K multiple of 16; N may be ragged AND odd (V=50257):
// B-side vector loads are only used when N % 4 == 0.

__device__ __forceinline__ unsigned f2tf(float x) {
    unsigned u;
    asm("cvt.rna.tf32.f32 %0, %1;" : "=r"(u) : "f"(x));
    return u;
}

#define SMP 136   // padded smem row stride

template <int EPI>  // bit0: +bias[n], bit1: relu, bit2: +resid[m,n]
__global__ __launch_bounds__(256)
void mma_gemm(const float* __restrict__ A, const float* __restrict__ B,
              const float* __restrict__ bias, const float* __restrict__ resid,
              float* __restrict__ C, int M, int N, int K) {
    __shared__ unsigned As[16][SMP];
    __shared__ unsigned Bs[16][SMP];
    const int tid  = threadIdx.x;
    const int lane = tid & 31;
    const int warp = tid >> 5;
    const int wm = (warp >> 2) * 64;   // warp row offset within block
    const int wn = (warp & 3) * 32;    // warp col offset within block
    const int row0 = blockIdx.y * 128, col0 = blockIdx.x * 128;
    // vectorized B loads only when rows stay 16B-aligned and tile is full
    const bool bvec = ((N & 3) == 0) && (col0 + 128 <= N);

    float acc[4][4][4];
#pragma unroll
    for (int mf = 0; mf < 4; mf++)
#pragma unroll
        for (int nf = 0; nf < 4; nf++)
#pragma unroll
            for (int j = 0; j < 4; j++) acc[mf][nf][j] = 0.0f;

    // prefetch registers
    float4 pa[2];
    float  pb[2][4];

    const int KT = K / 16;

    // initial load (k0 = 0)
#pragma unroll
    for (int i = 0; i < 2; i++) {
        int idx = tid * 2 + i; int r = idx >> 2, kc = idx & 3;
        pa[i] = *reinterpret_cast<const float4*>(A + (size_t)(row0 + r) * K + kc * 4);
    }
    if (bvec) {
#pragma unroll
        for (int i = 0; i < 2; i++) {
            int idx = tid * 2 + i; int k = idx >> 5, nc = idx & 31;
            float4 v = *reinterpret_cast<const float4*>(B + (size_t)k * N + col0 + nc * 4);
            pb[i][0] = v.x; pb[i][1] = v.y; pb[i][2] = v.z; pb[i][3] = v.w;
        }
    } else {
#pragma unroll
        for (int i = 0; i < 2; i++) {
            int idx = tid * 2 + i; int k = idx >> 5, nc = idx & 31;
            const float* src = B + (size_t)k * N + col0 + nc * 4;
#pragma unroll
            for (int j = 0; j < 4; j++) {
                int n = col0 + nc * 4 + j;
                pb[i][j] = (n < N) ? src[j] : 0.0f;
            }
        }
    }

    for (int kt = 0; kt < KT; kt++) {
        // store prefetched tile to smem (converted to tf32)
#pragma unroll
        for (int i = 0; i < 2; i++) {
            int idx = tid * 2 + i; int r = idx >> 2, kc = idx & 3;
            As[kc * 4 + 0][r] = f2tf(pa[i].x);
            As[kc * 4 + 1][r] = f2tf(pa[i].y);
            As[kc * 4 + 2][r] = f2tf(pa[i].z);
            As[kc * 4 + 3][r] = f2tf(pa[i].w);
        }
#pragma unroll
        for (int i = 0; i < 2; i++) {
            int idx = tid * 2 + i; int k = idx >> 5, nc = idx & 31;
#pragma unroll
            for (int j = 0; j < 4; j++) Bs[k][nc * 4 + j] = f2tf(pb[i][j]);
        }
        __syncthreads();

        // prefetch next tile
        if (kt + 1 < KT) {
            int k0 = (kt + 1) * 16;
#pragma unroll
            for (int i = 0; i < 2; i++) {
                int idx = tid * 2 + i; int r = idx >> 2, kc = idx & 3;
                pa[i] = *reinterpret_cast<const float4*>(A + (size_t)(row0 + r) * K + k0 + kc * 4);
            }
            if (bvec) {
#pragma unroll
                for (int i = 0; i < 2; i++) {
                    int idx = tid * 2 + i; int k = idx >> 5, nc = idx & 31;
                    float4 v = *reinterpret_cast<const float4*>(B + (size_t)(k0 + k) * N + col0 + nc * 4);
                    pb[i][0] = v.x; pb[i][1] = v.y; pb[i][2] = v.z; pb[i][3] = v.w;
                }
            } else {
#pragma unroll
                for (int i = 0; i < 2; i++) {
                    int idx = tid * 2 + i; int k = idx >> 5, nc = idx & 31;
                    const float* src = B + (size_t)(k0 + k) * N + col0 + nc * 4;
#pragma unroll
                    for (int j = 0; j < 4; j++) {
                        int n = col0 + nc * 4 + j;
                        pb[i][j] = (n < N) ? src[j] : 0.0f;
                    }
                }
            }
        }

        // compute: two k8 steps
#pragma unroll
        for (int ks = 0; ks < 16; ks += 8) {
            unsigned af[4][4], bf[4][2];
            const int kq = ks + (lane & 3);
            const int g  = lane >> 2;
#pragma unroll
            for (int mf = 0; mf < 4; mf++) {
                int m = wm + mf * 16 + g;
                af[mf][0] = As[kq][m];
                af[mf][1] = As[kq][m + 8];
                af[mf][2] = As[kq + 4][m];
                af[mf][3] = As[kq + 4][m + 8];
            }
#pragma unroll
            for (int nf = 0; nf < 4; nf++) {
                int n = wn + nf * 8 + g;
                bf[nf][0] = Bs[kq][n];
                bf[nf][1] = Bs[kq + 4][n];
            }
#pragma unroll
            for (int mf = 0; mf < 4; mf++)
#pragma unroll
                for (int nf = 0; nf < 4; nf++)
                    asm volatile(
                        "mma.sync.aligned.m16n8k8.row.col.f32.tf32.tf32.f32 "
                        "{%0,%1,%2,%3}, {%4,%5,%6,%7}, {%8,%9}, {%0,%1,%2,%3};"
                        : "+f"(acc[mf][nf][0]), "+f"(acc[mf][nf][1]),
                          "+f"(acc[mf][nf][2]), "+f"(acc[mf][nf][3])
                        : "r"(af[mf][0]), "r"(af[mf][1]), "r"(af[mf][2]), "r"(af[mf][3]),
                          "r"(bf[nf][0]), "r"(bf[nf][1]));
        }
        __syncthreads();
    }

    // epilogue: c0=(r,n) c1=(r,n+1) c2=(r+8,n) c3=(r+8,n+1)
#pragma unroll
    for (int mf = 0; mf < 4; mf++) {
        int r0 = row0 + wm + mf * 16 + (lane >> 2);
#pragma unroll
        for (int nf = 0; nf < 4; nf++) {
            int n0 = col0 + wn + nf * 8 + 2 * (lane & 3);
#pragma unroll
            for (int half = 0; half < 2; half++) {
                int r = r0 + half * 8;
#pragma unroll
                for (int j = 0; j < 2; j++) {
                    int n = n0 + j;
                    if (n < N) {
                        float v = acc[mf][nf][half * 2 + j];
                        if (EPI & 1) v += bias[n];
                        if (EPI & 2) v = fmaxf(v, 0.0f);
                        if (EPI & 4) v += resid[(size_t)r * N + n];
                        C[(size_t)r * N + n] = v;
                    }
                }
            }
        }
    }
}

// ---------------- streaming causal attention (warp = 4 queries) ------------
__global__ __launch_bounds__(256)
void attn_kernel(const float* __restrict__ qkv, float* __restrict__ o) {
    int wid = blockIdx.x * 8 + (threadIdx.x >> 5);
    int lane = threadIdx.x & 31;
    const int warps_per_head = NT / 4;  // 512
    int bh = wid / warps_per_head;
    int t0 = (wid % warps_per_head) * 4;
    int b = bh / NH, h = bh % NH;

    const float* base = qkv + (size_t)b * NT * NQKV;
    const float* qb = base + h * NHS;
    const float* kb = base + ND + h * NHS;
    const float* vb = base + 2 * ND + h * NHS;

    float q0[4], q1[4];
#pragma unroll
    for (int i = 0; i < 4; i++) {
        q0[i] = qb[(size_t)(t0 + i) * NQKV + lane];
        q1[i] = qb[(size_t)(t0 + i) * NQKV + 32 + lane];
    }
    float m[4], l[4], a0[4], a1[4];
#pragma unroll
    for (int i = 0; i < 4; i++) { m[i] = -1e30f; l[i] = 0.f; a0[i] = 0.f; a1[i] = 0.f; }

    const float scale = 0.125f;  // HS^-0.5
    int send = t0 + 3;
    for (int s = 0; s <= send; s++) {
        size_t off = (size_t)s * NQKV + lane;
        float k0v = kb[off], k1v = kb[off + 32];
        float v0v = vb[off], v1v = vb[off + 32];
#pragma unroll
        for (int i = 0; i < 4; i++) {
            float p = q0[i] * k0v + q1[i] * k1v;
            p += __shfl_xor_sync(0xffffffffu, p, 16);
            p += __shfl_xor_sync(0xffffffffu, p, 8);
            p += __shfl_xor_sync(0xffffffffu, p, 4);
            p += __shfl_xor_sync(0xffffffffu, p, 2);
            p += __shfl_xor_sync(0xffffffffu, p, 1);
            if (s <= t0 + i) {
                float sc = p * scale;
                float mn = fmaxf(m[i], sc);
                float corr = __expf(m[i] - mn);
                float e = __expf(sc - mn);
                l[i]  = l[i]  * corr + e;
                a0[i] = a0[i] * corr + e * v0v;
                a1[i] = a1[i] * corr + e * v1v;
                m[i] = mn;
            }
        }
    }
#pragma unroll
    for (int i = 0; i < 4; i++) {
        size_t oo = (size_t)(b * NT + t0 + i) * ND + h * NHS + lane;
        o[oo]      = a0[i] / l[i];
        o[oo + 32] = a1[i] / l[i];
    }
}

// ---------------- loss: one block per row over V=50257 ---------------------
__global__ __launch_bounds__(256)
void loss_kernel(const float* __restrict__ logits, const int* __restrict__ targets) {
    __shared__ float sm_[256], sl_[256];
    int row = blockIdx.x, tid = threadIdx.x;
    const float* lr = logits + (size_t)row * NV;
    float m = -1e30f, l = 0.0f;
    for (int j = tid; j < NV; j += 256) {
        float v = lr[j];
        float mn = fmaxf(m, v);
        l = l * __expf(m - mn) + __expf(v - mn);
        m = mn;
    }
    sm_[tid] = m; sl_[tid] = l;
    __syncthreads();
    for (int off = 128; off; off >>= 1) {
        if (tid < off) {
            float m2 = sm_[tid + off], l2 = sl_[tid + off];
            float mn = fmaxf(sm_[tid], m2);
            sl_[tid] = sl_[tid] * __expf(sm_[tid] - mn) + l2 * __expf(m2 - mn);
            sm_[tid] = mn;
        }
        __syncthreads();
    }
    if (tid == 0) {
        float lp = lr[targets[row]] - sm_[0] - logf(sl_[0]);
        atomicAdd(&g_loss, -lp * (1.0f / NTOK));
    }
}

__global__ void finalize_loss_kernel(float* out, int out_size) {
    long long pos = (long long)NTOK * NV;
    if ((long long)out_size > pos) out[pos] = g_loss;
}

// ---------------- host orchestration ----------------------------------------
extern "C" void kernel_launch(void* const* d_in, const int* in_sizes, int n_in,
                              void* d_out, int out_size) {
    const int*   idx     = (const int*)d_in[0];
    const int*   targets = (const int*)d_in[1];
    const float* tok_emb = (const float*)d_in[2];
    const float* pos_emb = (const float*)d_in[3];
    const float* wq      = (const float*)d_in[4];
    const float* wk      = (const float*)d_in[5];
    const float* wv      = (const float*)d_in[6];
    const float* wo      = (const float*)d_in[7];
    const float* bo      = (const float*)d_in[8];
    const float* ln1_s   = (const float*)d_in[9];
    const float* ln1_b   = (const float*)d_in[10];
    const float* ln2_s   = (const float*)d_in[11];
    const float* ln2_b   = (const float*)d_in[12];
    const float* w1      = (const float*)d_in[13];
    const float* b1      = (const float*)d_in[14];
    const float* w2      = (const float*)d_in[15];
    const float* b2      = (const float*)d_in[16];
    const float* lnf_s   = (const float*)d_in[17];
    const float* lnf_b   = (const float*)d_in[18];
    const float* head_w  = (const float*)d_in[19];
    const float* head_b  = (const float*)d_in[20];
    float* out = (float*)d_out;
    (void)in_sizes; (void)n_in;

    float *px, *ph, *pqkv, *po, *pmlp, *pw;
    cudaGetSymbolAddress((void**)&px,   g_x);
    cudaGetSymbolAddress((void**)&ph,   g_h);
    cudaGetSymbolAddress((void**)&pqkv, g_qkv);
    cudaGetSymbolAddress((void**)&po,   g_o);
    cudaGetSymbolAddress((void**)&pmlp, g_mlp);
    cudaGetSymbolAddress((void**)&pw,   g_wqkv);

    reset_loss_kernel<<<1, 1>>>();
    {
        int total = NL * ND * NQKV;
        repack_qkv_kernel<<<(total + 255) / 256, 256>>>(wq, wk, wv);
    }
    {
        int total = NTOK * ND;
        embed_kernel<<<(total + 255) / 256, 256>>>(idx, tok_emb, pos_emb);
    }

    dim3 gQKV((NQKV + 127) / 128, NTOK / 128);
    dim3 gD((ND + 127) / 128, NTOK / 128);
    dim3 gFF((NFF + 127) / 128, NTOK / 128);
    dim3 gV((NV + 127) / 128, NTOK / 128);

    for (int l = 0; l < NL; l++) {
        ln_kernel<<<NTOK, 256>>>(px, ln1_s + l * ND, ln1_b + l * ND, ph);
        mma_gemm<0><<<gQKV, 256>>>(ph, pw + (size_t)l * ND * NQKV,
                                   nullptr, nullptr, pqkv, NTOK, NQKV, ND);
        attn_kernel<<<NB * NH * NT / 4 / 8, 256>>>(pqkv, po);
        mma_gemm<5><<<gD, 256>>>(po, wo + (size_t)l * ND * ND,
                                 bo + l * ND, px, px, NTOK, ND, ND);
        ln_kernel<<<NTOK, 256>>>(px, ln2_s + l * ND, ln2_b + l * ND, ph);
        mma_gemm<3><<<gFF, 256>>>(ph, w1 + (size_t)l * ND * NFF,
                                  b1 + l * NFF, nullptr, pmlp, NTOK, NFF, ND);
        mma_gemm<5><<<gD, 256>>>(pmlp, w2 + (size_t)l * NFF * ND,
                                 b2 + l * ND, px, px, NTOK, ND, NFF);
    }

    ln_kernel<<<NTOK, 256>>>(px, lnf_s, lnf_b, ph);
    mma_gemm<1><<<gV, 256>>>(ph, head_w, head_b, nullptr, out, NTOK, NV, ND);
    loss_kernel<<<NTOK, 256>>>(out, targets);
    finalize_loss_kernel<<<1, 1>>>(out, out_size);
}